// round 11
// baseline (speedup 1.0000x reference)
#include <cuda_runtime.h>
#include <cstddef>
#include <cstdint>

// Problem constants (match reference)
#define BB 4
#define CC 256
#define HH 512
#define WW 512
#define NROIS 32
#define OUT 7
#define TS 68        // smem tile row stride in floats (16B-aligned, 17 chunks)
#define KP 4         // planes (channels) per CTA
#define HR 32        // max rows per half-plane buffer

__device__ int4 g_boxes[NROIS];

__device__ __forceinline__ void cp_async16(uint32_t smem_dst, const void* gmem_src) {
    asm volatile("cp.async.cg.shared.global [%0], [%1], 16;\n"
                 :: "r"(smem_dst), "l"(gmem_src));
}
__device__ __forceinline__ void cp_commit() {
    asm volatile("cp.async.commit_group;\n" ::: "memory");
}
template <int N>
__device__ __forceinline__ void cp_wait() {
    asm volatile("cp.async.wait_group %0;\n" :: "n"(N) : "memory");
}

// Decode ROI boxes once (handles int64-vs-int32 harness dtype ambiguity).
__global__ void decode_rois_kernel(const void* __restrict__ rois_raw) {
    int t = threadIdx.x;   // 0..31
    const long long* r64 = (const long long*)rois_raw;
    const int*       r32 = (const int*)rois_raw;
    long long p0 = r64[0], p1 = r64[1], p2 = r64[2], p3 = r64[3];
    bool is64 = (p0 >= 0 && p0 <= WW) && (p1 >= 0 && p1 <= HH) &&
                (p2 > p0 && p2 <= WW) && (p3 > p1 && p3 <= HH);
    int4 box;
    if (is64) {
        box = make_int4((int)r64[t * 4 + 0], (int)r64[t * 4 + 1],
                        (int)r64[t * 4 + 2], (int)r64[t * 4 + 3]);
    } else {
        box = make_int4(r32[t * 4 + 0], r32[t * 4 + 1],
                        r32[t * 4 + 2], r32[t * 4 + 3]);
    }
    g_boxes[t] = box;
}

// One CTA per (roi, b, c-group-of-4), 128 threads.
// Half-plane double-buffered cp.async pipeline (as R10).
// Compute: warp-collective vertical float4 column sums (LDS.128), then a tiny
// 49-thread horizontal pass from a 1.9 KB colsum array.
__global__ __launch_bounds__(128)
void roi_adaptive_pool_kernel(const float* __restrict__ x,
                              float* __restrict__ out)
{
    int bid = blockIdx.x;
    int cg  = bid & (CC / KP - 1);    // 0..63
    int t   = bid >> 6;
    int b   = t & (BB - 1);
    int roi = t >> 2;

    int4 box = g_boxes[roi];
    int x1 = box.x, y1 = box.y, x2 = box.z, y2 = box.w;

    int w  = x2 - x1;                  // 16..63
    int h  = y2 - y1;                  // 16..63
    int h0 = (h + 1) >> 1;             // balanced split, <= 32
    int xa = x1 & ~3;                  // 16B-aligned row start
    int ox = x1 - xa;                  // 0..3
    int nc = (x2 - xa + 3) >> 2;       // float4 chunks per row (4..17)

    __shared__ float tile[2][HR * TS]; // 2 x 8704 B
    __shared__ float colsum[OUT][TS];  // 1904 B

    int c0 = cg * KP;
    const float* plane0 = x + ((size_t)(b * CC + c0)) * (HH * WW);

    // ---- staging geometry (warp covers a row pair; all 32 lanes used) ----
    int lane  = threadIdx.x & 31;
    int warp  = threadIdx.x >> 5;
    int laneA = lane & 15;             // chunk index for staging
    int half  = lane >> 4;             // row of the pair
    int ncm   = nc < 16 ? nc : 16;
    bool doA  = laneA < ncm;
    bool doX  = (nc > 16) && (laneA == 15);   // rare 17th chunk
    int r0    = 2 * warp + half;       // 0..7

    const char* gwarp = (const char*)(plane0 + (size_t)y1 * WW + xa)
                        + (size_t)r0 * (WW * 4) + laneA * 16;
    uint32_t sb[2];
    sb[0] = (uint32_t)__cvta_generic_to_shared(tile[0])
            + (uint32_t)(r0 * TS + laneA * 4) * 4u;
    sb[1] = (uint32_t)__cvta_generic_to_shared(tile[1])
            + (uint32_t)(r0 * TS + laneA * 4) * 4u;

    // ---- vertical-reduction geometry: warp owns row-groups {warp, warp+4} --
    bool laneActive = lane < nc;                 // lane = chunk index (<=17)
    int g0  = warp;
    int g1  = warp + 4;
    bool hasB = g1 < OUT;
    int hsA = (g0 * h) / OUT, heA = ((g0 + 1) * h + OUT - 1) / OUT;
    int hsB = 0, heB = 0;
    if (hasB) { hsB = (g1 * h) / OUT; heB = ((g1 + 1) * h + OUT - 1) / OUT; }

    // ---- horizontal (bin) geometry: 49 threads ----
    int tb = threadIdx.x;
    int bi = tb / OUT;                 // valid for tb < 49
    int bj = tb - bi * OUT;
    int bhs = 0, bhe = 0, bws = 0, bwe = 0, ncol = 0;
    float inv_area = 0.f;
    if (tb < OUT * OUT) {
        bhs = (bi * h) / OUT;  bhe = ((bi + 1) * h + OUT - 1) / OUT;
        bws = (bj * w) / OUT;  bwe = ((bj + 1) * w + OUT - 1) / OUT;
        ncol = bwe - bws;
        inv_area = 1.0f / (float)((bhe - bhs) * ncol);
    }
    int coff = ox + bws;
    size_t obase = (((size_t)b * (NROIS * CC)) + (size_t)roi * CC + c0)
                   * (OUT * OUT) + tb;

    // ---- stage half-plane: stage index st = 2*k + hh ----
    auto stage = [&](int st) {
        int k      = st >> 1;
        int hh     = st & 1;
        int rstart = hh ? h0 : 0;
        int rend   = hh ? h  : h0;
        const char* gp = gwarp + (size_t)k * (HH * WW * 4)
                               + (size_t)rstart * (WW * 4);
        uint32_t dp = sb[st & 1];
        for (int r = rstart + r0; r < rend; r += 8) {
            if (doA) cp_async16(dp, gp);
            if (doX) cp_async16(dp + 16u, gp + 16);
            gp += 8 * WW * 4;
            dp += 8u * TS * 4u;
        }
        cp_commit();
    };

    float4 accA = make_float4(0.f, 0.f, 0.f, 0.f);
    float4 accB = make_float4(0.f, 0.f, 0.f, 0.f);

    stage(0);
    #pragma unroll
    for (int st = 0; st < 2 * KP; ++st) {
        if (st + 1 < 2 * KP) { stage(st + 1); cp_wait<1>(); }
        else                 { cp_wait<0>(); }
        __syncthreads();

        int hh     = st & 1;
        int rstart = hh ? h0 : 0;
        int rend   = hh ? h  : h0;
        const float* buf = tile[st & 1];

        if (laneActive) {
            // group A rows within this buffer
            int lo = hsA > rstart ? hsA : rstart;
            int hi = heA < rend   ? heA : rend;
            const float4* p4 = (const float4*)(buf + (lo - rstart) * TS) + lane;
            for (int r = lo; r < hi; ++r) {
                float4 v = *p4;
                accA.x += v.x; accA.y += v.y; accA.z += v.z; accA.w += v.w;
                p4 += TS / 4;
            }
            if (hasB) {
                int lo2 = hsB > rstart ? hsB : rstart;
                int hi2 = heB < rend   ? heB : rend;
                const float4* q4 = (const float4*)(buf + (lo2 - rstart) * TS) + lane;
                for (int r = lo2; r < hi2; ++r) {
                    float4 v = *q4;
                    accB.x += v.x; accB.y += v.y; accB.z += v.z; accB.w += v.w;
                    q4 += TS / 4;
                }
            }
        }

        if (hh) {   // plane complete: publish colsums, then bin pass
            if (laneActive) {
                *((float4*)colsum[g0] + lane) = accA;
                if (hasB) *((float4*)colsum[g1] + lane) = accB;
            }
            accA = make_float4(0.f, 0.f, 0.f, 0.f);
            accB = make_float4(0.f, 0.f, 0.f, 0.f);
            __syncthreads();

            if (tb < OUT * OUT) {
                const float* cs = colsum[bi] + coff;
                float s = 0.0f;
                #pragma unroll 4
                for (int cc = 0; cc < ncol; ++cc)
                    s += cs[cc];
                out[obase + (size_t)(st >> 1) * (OUT * OUT)] = s * inv_area;
            }
        }
        __syncthreads();   // buffer st&1 reused by stage(st+2)
    }
}

extern "C" void kernel_launch(void* const* d_in, const int* in_sizes, int n_in,
                              void* d_out, int out_size)
{
    const float* x    = (const float*)d_in[0];
    const void*  rois = d_in[1];
    float*       out  = (float*)d_out;

    decode_rois_kernel<<<1, NROIS>>>(rois);
    roi_adaptive_pool_kernel<<<NROIS * BB * (CC / KP), 128>>>(x, out);
}

// round 12
// speedup vs baseline: 1.1258x; 1.1258x over previous
#include <cuda_runtime.h>
#include <cstddef>
#include <cstdint>

// Problem constants (match reference)
#define BB 4
#define CC 256
#define HH 512
#define WW 512
#define NROIS 32
#define OUT 7
#define TS 68        // smem tile row stride in floats (16B-aligned)
#define KP 4         // planes (channels) per CTA
#define HR 32        // max rows per half-plane buffer

__device__ int4 g_boxes[NROIS];

__device__ __forceinline__ void cp_async16(uint32_t smem_dst, const void* gmem_src) {
    asm volatile("cp.async.cg.shared.global [%0], [%1], 16;\n"
                 :: "r"(smem_dst), "l"(gmem_src));
}
__device__ __forceinline__ void cp_commit() {
    asm volatile("cp.async.commit_group;\n" ::: "memory");
}
template <int N>
__device__ __forceinline__ void cp_wait() {
    asm volatile("cp.async.wait_group %0;\n" :: "n"(N) : "memory");
}

// Decode ROI boxes once (handles int64-vs-int32 harness dtype ambiguity).
__global__ void decode_rois_kernel(const void* __restrict__ rois_raw) {
    int t = threadIdx.x;   // 0..31
    const long long* r64 = (const long long*)rois_raw;
    const int*       r32 = (const int*)rois_raw;
    long long p0 = r64[0], p1 = r64[1], p2 = r64[2], p3 = r64[3];
    bool is64 = (p0 >= 0 && p0 <= WW) && (p1 >= 0 && p1 <= HH) &&
                (p2 > p0 && p2 <= WW) && (p3 > p1 && p3 <= HH);
    int4 box;
    if (is64) {
        box = make_int4((int)r64[t * 4 + 0], (int)r64[t * 4 + 1],
                        (int)r64[t * 4 + 2], (int)r64[t * 4 + 3]);
    } else {
        box = make_int4(r32[t * 4 + 0], r32[t * 4 + 1],
                        r32[t * 4 + 2], r32[t * 4 + 3]);
    }
    g_boxes[t] = box;
}

// One CTA per (roi, b, c-group-of-4), 128 threads.
// Half-plane double-buffered cp.async pipeline (R10 compute scheme).
// bid mapping: roi FASTEST so every scheduling wave mixes all ROI sizes
// (wave-duration balance; ROI areas span a 15x range).
__global__ __launch_bounds__(128)
void roi_adaptive_pool_kernel(const float* __restrict__ x,
                              float* __restrict__ out)
{
    int bid  = blockIdx.x;
    int roi  = bid & (NROIS - 1);     // fastest dim -> balanced waves
    int rest = bid >> 5;
    int cg   = rest & (CC / KP - 1);  // 0..63
    int b    = rest >> 6;

    int4 box = g_boxes[roi];
    int x1 = box.x, y1 = box.y, x2 = box.z, y2 = box.w;

    int w  = x2 - x1;                  // 16..63
    int h  = y2 - y1;                  // 16..63
    int h0 = (h + 1) >> 1;             // balanced split, <= 32
    int xa = x1 & ~3;                  // 16B-aligned row start
    int ox = x1 - xa;                  // 0..3
    int nc = (x2 - xa + 3) >> 2;       // float4 chunks per row (4..17)

    __shared__ float tile[2][HR * TS]; // 2 x 8704 B

    int c0 = cg * KP;
    const float* plane0 = x + ((size_t)(b * CC + c0)) * (HH * WW);

    // ---- staging geometry (warp covers a row pair; all 32 lanes used) ----
    int lane  = threadIdx.x & 31;
    int warp  = threadIdx.x >> 5;
    int laneA = lane & 15;             // chunk index
    int half  = lane >> 4;             // row of the pair
    int ncm   = nc < 16 ? nc : 16;
    bool doA  = laneA < ncm;
    bool doX  = (nc > 16) && (laneA == 15);   // rare 17th chunk
    int r0    = 2 * warp + half;       // 0..7

    const char* gwarp = (const char*)(plane0 + (size_t)y1 * WW + xa)
                        + (size_t)r0 * (WW * 4) + laneA * 16;
    uint32_t sb[2];
    sb[0] = (uint32_t)__cvta_generic_to_shared(tile[0])
            + (uint32_t)(r0 * TS + laneA * 4) * 4u;
    sb[1] = (uint32_t)__cvta_generic_to_shared(tile[1])
            + (uint32_t)(r0 * TS + laneA * 4) * 4u;

    // ---- phase-2 geometry (hoisted; identical for all planes) ----
    int tb  = threadIdx.x;
    int bin = tb >> 1;
    if (bin > 48) bin = 48;            // keep warp 3 converged
    int p = tb & 1;
    int i = bin / 7;
    int j = bin - i * 7;
    int hs = (i * h) / OUT;
    int he = ((i + 1) * h + OUT - 1) / OUT;
    int ws = (j * w) / OUT;
    int we = ((j + 1) * w + OUT - 1) / OUT;
    int ncol = we - ws;
    float inv_area = 1.0f / (float)((he - hs) * ncol);
    bool writer = (p == 0) && (tb < 2 * OUT * OUT);
    size_t obase = (((size_t)b * (NROIS * CC)) + (size_t)roi * CC + c0)
                   * (OUT * OUT) + bin;
    int coff = ox + ws;

    // ---- stage half-plane: stage index st = 2*k + hh ----
    auto stage = [&](int st) {
        int k      = st >> 1;
        int hh     = st & 1;
        int rstart = hh ? h0 : 0;
        int rend   = hh ? h  : h0;
        const char* gp = gwarp + (size_t)k * (HH * WW * 4)
                               + (size_t)rstart * (WW * 4);
        uint32_t dp = sb[st & 1];
        for (int r = rstart + r0; r < rend; r += 8) {
            if (doA) cp_async16(dp, gp);
            if (doX) cp_async16(dp + 16u, gp + 16);
            gp += 8 * WW * 4;
            dp += 8u * TS * 4u;
        }
        cp_commit();
    };

    float acc = 0.0f;
    stage(0);
    #pragma unroll
    for (int st = 0; st < 2 * KP; ++st) {
        if (st + 1 < 2 * KP) { stage(st + 1); cp_wait<1>(); }
        else                 { cp_wait<0>(); }
        __syncthreads();

        int hh     = st & 1;
        int rstart = hh ? h0 : 0;
        int rend   = hh ? h  : h0;

        // this thread's bin rows (parity p) clipped to [rstart, rend)
        int rr = hs + p;
        if (rr < rstart) rr += (rstart - rr + 1) & ~1;   // keep parity
        int rlim = he < rend ? he : rend;

        const float* row = tile[st & 1] + (rr - rstart) * TS + coff;
        for (; rr < rlim; rr += 2) {
            #pragma unroll 4
            for (int cc = 0; cc < ncol; ++cc)
                acc += row[cc];
            row += 2 * TS;
        }

        if (hh) {   // plane complete: combine parity halves and write
            float s = acc + __shfl_xor_sync(0xffffffffu, acc, 1);
            if (writer)
                out[obase + (size_t)(st >> 1) * (OUT * OUT)] = s * inv_area;
            acc = 0.0f;
        }
        __syncthreads();   // buffer st&1 reused by stage(st+2)
    }
}

extern "C" void kernel_launch(void* const* d_in, const int* in_sizes, int n_in,
                              void* d_out, int out_size)
{
    const float* x    = (const float*)d_in[0];
    const void*  rois = d_in[1];
    float*       out  = (float*)d_out;

    decode_rois_kernel<<<1, NROIS>>>(rois);
    roi_adaptive_pool_kernel<<<NROIS * BB * (CC / KP), 128>>>(x, out);
}

// round 13
// speedup vs baseline: 1.1276x; 1.0015x over previous
#include <cuda_runtime.h>
#include <cstddef>
#include <cstdint>

// Problem constants (match reference)
#define BB 4
#define CC 256
#define HH 512
#define WW 512
#define NROIS 32
#define OUT 7
#define TS 68        // smem tile row stride in floats (16B-aligned, 17 chunks)
#define KP 4         // planes (channels) per CTA
#define NT 224       // 7 warps: one per output row group

__device__ int4 g_boxes[NROIS];

__device__ __forceinline__ void cp_async16(uint32_t smem_dst, const void* gmem_src) {
    asm volatile("cp.async.cg.shared.global [%0], [%1], 16;\n"
                 :: "r"(smem_dst), "l"(gmem_src));
}
__device__ __forceinline__ void cp_commit() {
    asm volatile("cp.async.commit_group;\n" ::: "memory");
}
template <int N>
__device__ __forceinline__ void cp_wait() {
    asm volatile("cp.async.wait_group %0;\n" :: "n"(N) : "memory");
}
__device__ __forceinline__ void addf32x2(unsigned long long& acc, unsigned long long v) {
    asm("add.rn.f32x2 %0, %0, %1;" : "+l"(acc) : "l"(v));
}

// Decode ROI boxes once (handles int64-vs-int32 harness dtype ambiguity).
__global__ void decode_rois_kernel(const void* __restrict__ rois_raw) {
    int t = threadIdx.x;   // 0..31
    const long long* r64 = (const long long*)rois_raw;
    const int*       r32 = (const int*)rois_raw;
    long long p0 = r64[0], p1 = r64[1], p2 = r64[2], p3 = r64[3];
    bool is64 = (p0 >= 0 && p0 <= WW) && (p1 >= 0 && p1 <= HH) &&
                (p2 > p0 && p2 <= WW) && (p3 > p1 && p3 <= HH);
    int4 box;
    if (is64) {
        box = make_int4((int)r64[t * 4 + 0], (int)r64[t * 4 + 1],
                        (int)r64[t * 4 + 2], (int)r64[t * 4 + 3]);
    } else {
        box = make_int4(r32[t * 4 + 0], r32[t * 4 + 1],
                        r32[t * 4 + 2], r32[t * 4 + 3]);
    }
    g_boxes[t] = box;
}

// One CTA per (roi, b, c-group-of-4), 224 threads (7 warps).
// Full-plane double-buffered cp.async pipeline.
// Vertical: warp g reduces row-group g to float column sums via LDS.128 +
//           packed add.rn.f32x2 (3 instrs per 16 B).
// Horizontal: 49 threads sum <=10 colsum scalars each and write.
__global__ __launch_bounds__(NT)
void roi_adaptive_pool_kernel(const float* __restrict__ x,
                              float* __restrict__ out)
{
    int bid  = blockIdx.x;
    int roi  = bid & (NROIS - 1);     // fastest dim -> balanced waves
    int rest = bid >> 5;
    int cg   = rest & (CC / KP - 1);  // 0..63
    int b    = rest >> 6;

    int4 box = g_boxes[roi];
    int x1 = box.x, y1 = box.y, x2 = box.z, y2 = box.w;

    int w  = x2 - x1;                  // 16..63
    int h  = y2 - y1;                  // 16..63
    int xa = x1 & ~3;                  // 16B-aligned row start
    int ox = x1 - xa;                  // 0..3
    int nc = (x2 - xa + 3) >> 2;       // float4 chunks per row (4..17)

    __shared__ float tile[2][64 * TS];       // 2 x 17408 B
    __shared__ float colsum[OUT][TS];        // 1904 B

    int c0 = cg * KP;
    const float* plane0 = x + ((size_t)(b * CC + c0)) * (HH * WW);

    // ---- staging geometry: 7 warps, warp covers a row pair (stride 14) ----
    int lane  = threadIdx.x & 31;
    int warp  = threadIdx.x >> 5;      // 0..6
    int laneA = lane & 15;             // chunk index
    int half  = lane >> 4;             // row of the pair
    int ncm   = nc < 16 ? nc : 16;
    bool doA  = laneA < ncm;
    bool doX  = (nc > 16) && (laneA == 15);   // rare 17th chunk
    int r0    = 2 * warp + half;       // 0..13

    const char* gwarp = (const char*)(plane0 + (size_t)y1 * WW + xa)
                        + (size_t)r0 * (WW * 4) + laneA * 16;
    uint32_t sb[2];
    sb[0] = (uint32_t)__cvta_generic_to_shared(tile[0])
            + (uint32_t)(r0 * TS + laneA * 4) * 4u;
    sb[1] = (uint32_t)__cvta_generic_to_shared(tile[1])
            + (uint32_t)(r0 * TS + laneA * 4) * 4u;

    // ---- vertical geometry: warp g owns row-group g; lane = chunk ----
    bool laneActive = lane < nc;
    int ghs = (warp * h) / OUT;
    int ghe = ((warp + 1) * h + OUT - 1) / OUT;     // <= 10 rows

    // ---- horizontal geometry: 49 threads ----
    int tb = threadIdx.x;
    int bi = tb / OUT;
    int bj = tb - bi * OUT;
    int ncol = 0;
    float inv_area = 0.f;
    int coff = 0;
    if (tb < OUT * OUT) {
        int bhs = (bi * h) / OUT, bhe = ((bi + 1) * h + OUT - 1) / OUT;
        int bws = (bj * w) / OUT, bwe = ((bj + 1) * w + OUT - 1) / OUT;
        ncol = bwe - bws;
        inv_area = 1.0f / (float)((bhe - bhs) * ncol);
        coff = ox + bws;
    }
    size_t obase = (((size_t)b * (NROIS * CC)) + (size_t)roi * CC + c0)
                   * (OUT * OUT) + tb;

    // ---- stage one full plane into buffer k&1 ----
    auto stage = [&](int k) {
        const char* gp = gwarp + (size_t)k * (HH * WW * 4);
        uint32_t    dp = sb[k & 1];
        for (int r = r0; r < h; r += 14) {
            if (doA) cp_async16(dp, gp);
            if (doX) cp_async16(dp + 16u, gp + 16);
            gp += 14 * (WW * 4);
            dp += 14u * TS * 4u;
        }
        cp_commit();
    };

    stage(0);
    #pragma unroll
    for (int k = 0; k < KP; ++k) {
        if (k + 1 < KP) { stage(k + 1); cp_wait<1>(); }
        else            { cp_wait<0>(); }
        __syncthreads();

        // vertical: packed column sums for this warp's row group
        if (laneActive) {
            unsigned long long a01 = 0, a23 = 0;   // packed {0.f,0.f}
            const ulonglong2* p = (const ulonglong2*)(tile[k & 1] + ghs * TS) + lane;
            for (int r = ghs; r < ghe; ++r) {
                ulonglong2 v = *p;
                addf32x2(a01, v.x);
                addf32x2(a23, v.y);
                p += TS / 4;
            }
            ((ulonglong2*)colsum[warp])[lane] = make_ulonglong2(a01, a23);
        }
        __syncthreads();

        // horizontal: one thread per bin
        if (tb < OUT * OUT) {
            const float* cs = colsum[bi] + coff;
            float s = 0.0f;
            #pragma unroll 4
            for (int cc = 0; cc < ncol; ++cc)
                s += cs[cc];
            out[obase + (size_t)k * (OUT * OUT)] = s * inv_area;
        }
        __syncthreads();   // buffer k&1 reused by stage(k+2)
    }
}

extern "C" void kernel_launch(void* const* d_in, const int* in_sizes, int n_in,
                              void* d_out, int out_size)
{
    const float* x    = (const float*)d_in[0];
    const void*  rois = d_in[1];
    float*       out  = (float*)d_out;

    decode_rois_kernel<<<1, NROIS>>>(rois);
    roi_adaptive_pool_kernel<<<NROIS * BB * (CC / KP), NT>>>(x, out);
}

// round 14
// speedup vs baseline: 1.1399x; 1.0109x over previous
#include <cuda_runtime.h>
#include <cstddef>
#include <cstdint>

// Problem constants (match reference)
#define BB 4
#define CC 256
#define HH 512
#define WW 512
#define NROIS 32
#define OUT 7
#define TS 68        // smem tile row stride in floats (16B-aligned)
#define KP 4         // planes (channels) per CTA
#define HR 32        // max rows per half-plane buffer

__device__ __forceinline__ void cp_async16(uint32_t smem_dst, const void* gmem_src) {
    asm volatile("cp.async.cg.shared.global [%0], [%1], 16;\n"
                 :: "r"(smem_dst), "l"(gmem_src));
}
__device__ __forceinline__ void cp_commit() {
    asm volatile("cp.async.commit_group;\n" ::: "memory");
}
template <int N>
__device__ __forceinline__ void cp_wait() {
    asm volatile("cp.async.wait_group %0;\n" :: "n"(N) : "memory");
}

// One CTA per (roi, b, c-group-of-4), 128 threads.
// Half-plane double-buffered cp.async pipeline; roi is the FASTEST grid dim
// so every scheduling wave mixes all 32 ROI sizes (wave balance).
// Box decode inlined (int64-vs-int32 probe; L2-resident after wave 1).
__global__ __launch_bounds__(128)
void roi_adaptive_pool_kernel(const float* __restrict__ x,
                              const void* __restrict__ rois_raw,
                              float* __restrict__ out)
{
    int bid  = blockIdx.x;
    int roi  = bid & (NROIS - 1);     // fastest dim -> balanced waves
    int rest = bid >> 5;
    int cg   = rest & (CC / KP - 1);  // 0..63
    int b    = rest >> 6;

    // ---- inline dtype probe + box read ----
    const long long* r64 = (const long long*)rois_raw;
    const int*       r32 = (const int*)rois_raw;
    long long p0 = r64[0], p1 = r64[1], p2 = r64[2], p3 = r64[3];
    bool is64 = (p0 >= 0 && p0 <= WW) && (p1 >= 0 && p1 <= HH) &&
                (p2 > p0 && p2 <= WW) && (p3 > p1 && p3 <= HH);
    int x1, y1, x2, y2;
    if (is64) {
        const long long* r = r64 + (size_t)roi * 4;
        x1 = (int)r[0]; y1 = (int)r[1]; x2 = (int)r[2]; y2 = (int)r[3];
    } else {
        const int* r = r32 + (size_t)roi * 4;
        x1 = r[0]; y1 = r[1]; x2 = r[2]; y2 = r[3];
    }

    int w  = x2 - x1;                  // 16..63
    int h  = y2 - y1;                  // 16..63
    int h0 = (h + 1) >> 1;             // balanced split, <= 32
    int xa = x1 & ~3;                  // 16B-aligned row start
    int ox = x1 - xa;                  // 0..3
    int nc = (x2 - xa + 3) >> 2;       // float4 chunks per row (4..17)

    __shared__ float tile[2][HR * TS]; // 2 x 8704 B

    int c0 = cg * KP;
    const float* plane0 = x + ((size_t)(b * CC + c0)) * (HH * WW);

    // ---- staging geometry (warp covers a row pair; all 32 lanes used) ----
    int lane  = threadIdx.x & 31;
    int warp  = threadIdx.x >> 5;
    int laneA = lane & 15;             // chunk index
    int half  = lane >> 4;             // row of the pair
    int ncm   = nc < 16 ? nc : 16;
    bool doA  = laneA < ncm;
    bool doX  = (nc > 16) && (laneA == 15);   // rare 17th chunk
    int r0    = 2 * warp + half;       // 0..7

    const char* gwarp = (const char*)(plane0 + (size_t)y1 * WW + xa)
                        + (size_t)r0 * (WW * 4) + laneA * 16;
    uint32_t sb[2];
    sb[0] = (uint32_t)__cvta_generic_to_shared(tile[0])
            + (uint32_t)(r0 * TS + laneA * 4) * 4u;
    sb[1] = (uint32_t)__cvta_generic_to_shared(tile[1])
            + (uint32_t)(r0 * TS + laneA * 4) * 4u;

    // ---- phase-2 geometry (hoisted; identical for all planes) ----
    int tb  = threadIdx.x;
    int bin = tb >> 1;
    if (bin > 48) bin = 48;            // keep warp 3 converged
    int p = tb & 1;
    int i = bin / 7;
    int j = bin - i * 7;
    int hs = (i * h) / OUT;
    int he = ((i + 1) * h + OUT - 1) / OUT;
    int ws = (j * w) / OUT;
    int we = ((j + 1) * w + OUT - 1) / OUT;
    int ncol = we - ws;
    float inv_area = 1.0f / (float)((he - hs) * ncol);
    bool writer = (p == 0) && (tb < 2 * OUT * OUT);
    size_t obase = (((size_t)b * (NROIS * CC)) + (size_t)roi * CC + c0)
                   * (OUT * OUT) + bin;
    int coff = ox + ws;

    // ---- stage half-plane: stage index st = 2*k + hh ----
    auto stage = [&](int st) {
        int k      = st >> 1;
        int hh     = st & 1;
        int rstart = hh ? h0 : 0;
        int rend   = hh ? h  : h0;
        const char* gp = gwarp + (size_t)k * (HH * WW * 4)
                               + (size_t)rstart * (WW * 4);
        uint32_t dp = sb[st & 1];
        for (int r = rstart + r0; r < rend; r += 8) {
            if (doA) cp_async16(dp, gp);
            if (doX) cp_async16(dp + 16u, gp + 16);
            gp += 8 * WW * 4;
            dp += 8u * TS * 4u;
        }
        cp_commit();
    };

    float acc = 0.0f;
    stage(0);
    #pragma unroll
    for (int st = 0; st < 2 * KP; ++st) {
        if (st + 1 < 2 * KP) { stage(st + 1); cp_wait<1>(); }
        else                 { cp_wait<0>(); }
        __syncthreads();

        int hh     = st & 1;
        int rstart = hh ? h0 : 0;
        int rend   = hh ? h  : h0;

        // this thread's bin rows (parity p) clipped to [rstart, rend)
        int rr = hs + p;
        if (rr < rstart) rr += (rstart - rr + 1) & ~1;   // keep parity
        int rlim = he < rend ? he : rend;

        const float* row = tile[st & 1] + (rr - rstart) * TS + coff;
        for (; rr < rlim; rr += 2) {
            #pragma unroll 4
            for (int cc = 0; cc < ncol; ++cc)
                acc += row[cc];
            row += 2 * TS;
        }

        if (hh) {   // plane complete: combine parity halves and write
            float s = acc + __shfl_xor_sync(0xffffffffu, acc, 1);
            if (writer)
                out[obase + (size_t)(st >> 1) * (OUT * OUT)] = s * inv_area;
            acc = 0.0f;
        }
        __syncthreads();   // buffer st&1 reused by stage(st+2)
    }
}

extern "C" void kernel_launch(void* const* d_in, const int* in_sizes, int n_in,
                              void* d_out, int out_size)
{
    const float* x    = (const float*)d_in[0];
    const void*  rois = d_in[1];
    float*       out  = (float*)d_out;

    roi_adaptive_pool_kernel<<<NROIS * BB * (CC / KP), 128>>>(x, rois, out);
}

// round 15
// speedup vs baseline: 1.2124x; 1.0636x over previous
#include <cuda_runtime.h>
#include <cstddef>
#include <cstdint>

// Problem constants (match reference)
#define BB 4
#define CC 256
#define HH 512
#define WW 512
#define NROIS 32
#define OUT 7
#define TS 68        // row stride in floats (16B-aligned, 17 chunks)
#define KP 4         // planes (channels) per CTA
#define HRW 10       // max rows in one output row-group (h<=63 -> <=10)

__device__ __forceinline__ void cp_async16(uint32_t smem_dst, const void* gmem_src) {
    asm volatile("cp.async.cg.shared.global [%0], [%1], 16;\n"
                 :: "r"(smem_dst), "l"(gmem_src));
}
__device__ __forceinline__ void cp_commit() {
    asm volatile("cp.async.commit_group;\n" ::: "memory");
}
template <int N>
__device__ __forceinline__ void cp_wait() {
    asm volatile("cp.async.wait_group %0;\n" :: "n"(N) : "memory");
}

// One CTA per (roi, b, c-group-of-4), 224 threads = 7 autonomous warps.
// Warp g owns output row-group g: stages its own <=10 ROI rows into a
// warp-private double buffer (cp.async, one plane prefetched), reduces
// vertically to float4 column sums in registers, then lanes 0..6 finish
// the 7 bins of row g. NO __syncthreads anywhere -> warps stream
// independently and DRAM bursts decorrelate.
__global__ __launch_bounds__(224)
void roi_adaptive_pool_kernel(const float* __restrict__ x,
                              const void* __restrict__ rois_raw,
                              float* __restrict__ out)
{
    int bid  = blockIdx.x;
    int roi  = bid & (NROIS - 1);     // fastest dim -> balanced waves + L2 ROI-overlap reuse
    int rest = bid >> 5;
    int cg   = rest & (CC / KP - 1);  // 0..63
    int b    = rest >> 6;

    // ---- inline dtype probe + box read (L2-resident after wave 1) ----
    const long long* r64 = (const long long*)rois_raw;
    const int*       r32 = (const int*)rois_raw;
    long long p0 = r64[0], p1 = r64[1], p2 = r64[2], p3 = r64[3];
    bool is64 = (p0 >= 0 && p0 <= WW) && (p1 >= 0 && p1 <= HH) &&
                (p2 > p0 && p2 <= WW) && (p3 > p1 && p3 <= HH);
    int x1, y1, x2, y2;
    if (is64) {
        const long long* r = r64 + (size_t)roi * 4;
        x1 = (int)r[0]; y1 = (int)r[1]; x2 = (int)r[2]; y2 = (int)r[3];
    } else {
        const int* r = r32 + (size_t)roi * 4;
        x1 = r[0]; y1 = r[1]; x2 = r[2]; y2 = r[3];
    }

    int w  = x2 - x1;                  // 16..63
    int h  = y2 - y1;                  // 16..63
    int xa = x1 & ~3;                  // 16B-aligned row start
    int ox = x1 - xa;                  // 0..3
    int nc = (x2 - xa + 3) >> 2;       // float4 chunks per row (4..17)

    __shared__ float tile[OUT][2][HRW * TS];   // 7 x 2 x 2720 B = 38080 B
    __shared__ float colsum[OUT][TS];          // 1904 B

    int c0 = cg * KP;
    const float* plane0 = x + ((size_t)(b * CC + c0)) * (HH * WW);

    int lane = threadIdx.x & 31;
    int g    = threadIdx.x >> 5;       // warp id = output row group 0..6

    // this warp's row range
    int ghs = (g * h) / OUT;
    int ghe = ((g + 1) * h + OUT - 1) / OUT;   // ghe-ghs <= 10
    int nrows = ghe - ghs;

    // staging: laneA = chunk (0..15), half = row parity within group
    int laneA = lane & 15;
    int half  = lane >> 4;
    int ncm   = nc < 16 ? nc : 16;
    bool doA  = laneA < ncm;
    bool doX  = (nc > 16) && (laneA == 15);    // 17th chunk

    const char* gbase = (const char*)(plane0 + (size_t)(y1 + ghs + half) * WW + xa)
                        + laneA * 16;
    uint32_t sbw[2];
    sbw[0] = (uint32_t)__cvta_generic_to_shared(tile[g][0])
             + (uint32_t)(half * TS + laneA * 4) * 4u;
    sbw[1] = (uint32_t)__cvta_generic_to_shared(tile[g][1])
             + (uint32_t)(half * TS + laneA * 4) * 4u;

    // horizontal geometry for lanes 0..6 (bin (g, lane))
    int bws = 0, bwe = 0;
    float inv_area = 0.f;
    if (lane < OUT) {
        bws = (lane * w) / OUT;
        bwe = ((lane + 1) * w + OUT - 1) / OUT;
        inv_area = 1.0f / (float)(nrows * (bwe - bws));
    }
    size_t obase = (((size_t)b * (NROIS * CC)) + (size_t)roi * CC + c0)
                   * (OUT * OUT) + g * OUT + lane;

    // ---- stage plane k's row group into buffer k&1 (warp-private) ----
    auto stage = [&](int k) {
        const char* gp = gbase + (size_t)k * (HH * WW * 4);
        uint32_t    dp = sbw[k & 1];
        for (int r = half; r < nrows; r += 2) {
            if (doA) cp_async16(dp, gp);
            if (doX) cp_async16(dp + 16u, gp + 16);
            gp += 2 * (WW * 4);
            dp += 2u * TS * 4u;
        }
        cp_commit();
    };

    stage(0);
    #pragma unroll
    for (int k = 0; k < KP; ++k) {
        if (k + 1 < KP) { stage(k + 1); cp_wait<1>(); }
        else            { cp_wait<0>(); }
        __syncwarp();

        // vertical: lane = chunk, accumulate float4 column sums over nrows
        if (lane < nc) {
            float4 a = make_float4(0.f, 0.f, 0.f, 0.f);
            const float4* p = (const float4*)tile[g][k & 1] + lane;
            #pragma unroll 4
            for (int r = 0; r < nrows; ++r) {
                float4 v = *p;
                a.x += v.x; a.y += v.y; a.z += v.z; a.w += v.w;
                p += TS / 4;
            }
            ((float4*)colsum[g])[lane] = a;
        }
        __syncwarp();

        // horizontal: lanes 0..6 each finish one bin
        if (lane < OUT) {
            const float* cs = colsum[g] + ox + bws;
            int ncol = bwe - bws;
            float s = 0.0f;
            #pragma unroll 4
            for (int cc = 0; cc < ncol; ++cc)
                s += cs[cc];
            out[obase + (size_t)k * (OUT * OUT)] = s * inv_area;
        }
        __syncwarp();   // colsum[g] reused next plane
    }
}

extern "C" void kernel_launch(void* const* d_in, const int* in_sizes, int n_in,
                              void* d_out, int out_size)
{
    const float* x    = (const float*)d_in[0];
    const void*  rois = d_in[1];
    float*       out  = (float*)d_out;

    roi_adaptive_pool_kernel<<<NROIS * BB * (CC / KP), 224>>>(x, rois, out);
}